// round 14
// baseline (speedup 1.0000x reference)
#include <cuda_runtime.h>
#include <cuda_bf16.h>
#include <cstdint>
#include <cstddef>

// Problem constants
#define BB 64
#define TT 2048
#define FF 128
#define UU 128
#define GG 512               // 4*U
#define MM (BB * TT)         // 131072 rows of x

// Scratch buffers (static __device__; allocation is forbidden)
__device__ float g_Z[2ull * 131072ull * 512ull];                 // z = x@Wx + b, both dirs
__device__ __align__(16) __nv_bfloat16 g_XH[131072ull * 128ull]; // x hi (bf16)
__device__ __align__(16) __nv_bfloat16 g_XL[131072ull * 128ull]; // x lo
__device__ __align__(16) __nv_bfloat16 g_WtH[2ull * 512ull * 128ull]; // W_x^T hi [dir][n][k]
__device__ __align__(16) __nv_bfloat16 g_WtL[2ull * 512ull * 128ull]; // W_x^T lo

// ---------------- f32x2 packed helpers ----------------
__device__ __forceinline__ unsigned long long fma2(unsigned long long a,
                                                   unsigned long long b,
                                                   unsigned long long c) {
    unsigned long long d;
    asm("fma.rn.f32x2 %0, %1, %2, %3;" : "=l"(d) : "l"(a), "l"(b), "l"(c));
    return d;
}
__device__ __forceinline__ unsigned long long pk(float x, float y) {
    unsigned long long d;
    asm("mov.b64 %0, {%1, %2};" : "=l"(d) : "f"(x), "f"(y));
    return d;
}
__device__ __forceinline__ float2 upk(unsigned long long a) {
    float2 r;
    asm("mov.b64 {%0, %1}, %2;" : "=f"(r.x), "=f"(r.y) : "l"(a));
    return r;
}

// ---------------- activations (HW tanh unit) ----------------
__device__ __forceinline__ float tanhA(float x) {
    float y;
    asm("tanh.approx.f32 %0, %1;" : "=f"(y) : "f"(x));
    return y;
}
__device__ __forceinline__ float sigmA(float x) {
    return fmaf(0.5f, tanhA(0.5f * x), 0.5f);
}

// ---------------- mma.sync / cp.async helpers ----------------
__device__ __forceinline__ uint32_t smem_u32(const void* p) {
    uint32_t a;
    asm("{ .reg .u64 t; cvta.to.shared.u64 t, %1; cvt.u32.u64 %0, t; }" : "=r"(a) : "l"(p));
    return a;
}
__device__ __forceinline__ void ldsm_x4(uint32_t addr, uint32_t* r) {
    asm volatile("ldmatrix.sync.aligned.m8n8.x4.shared.b16 {%0,%1,%2,%3}, [%4];"
                 : "=r"(r[0]), "=r"(r[1]), "=r"(r[2]), "=r"(r[3]) : "r"(addr));
}
__device__ __forceinline__ void mma_bf16(float* c, const uint32_t* a,
                                         uint32_t b0, uint32_t b1) {
    asm volatile("mma.sync.aligned.m16n8k16.row.col.f32.bf16.bf16.f32 "
                 "{%0,%1,%2,%3}, {%4,%5,%6,%7}, {%8,%9}, {%0,%1,%2,%3};"
                 : "+f"(c[0]), "+f"(c[1]), "+f"(c[2]), "+f"(c[3])
                 : "r"(a[0]), "r"(a[1]), "r"(a[2]), "r"(a[3]), "r"(b0), "r"(b1));
}
#define CPA16(dst, src) \
    asm volatile("cp.async.cg.shared.global [%0], [%1], 16;" \
                 :: "r"(dst), "l"((const void*)(src)) : "memory")
#define CPA_COMMIT() asm volatile("cp.async.commit_group;" ::: "memory")
#define CPA_WAIT(n)  asm volatile("cp.async.wait_group %0;" :: "n"(n) : "memory")

// =====================================================================
// Prep 1: x (fp32) -> XH, XL (bf16 split). 8 elems/thread.
// =====================================================================
__global__ __launch_bounds__(256) void convert_x(const float* __restrict__ x) {
    size_t i = ((size_t)blockIdx.x * 256 + threadIdx.x) * 8;
    float4 a = *(const float4*)(x + i);
    float4 b = *(const float4*)(x + i + 4);
    float f[8] = {a.x, a.y, a.z, a.w, b.x, b.y, b.z, b.w};
    union { __nv_bfloat16 h[8]; uint4 u; } H, L;
#pragma unroll
    for (int e = 0; e < 8; e++) {
        __nv_bfloat16 hi = __float2bfloat16(f[e]);
        H.h[e] = hi;
        L.h[e] = __float2bfloat16(f[e] - __bfloat162float(hi));
    }
    *(uint4*)(g_XH + i) = H.u;
    *(uint4*)(g_XL + i) = L.u;
}

// =====================================================================
// Prep 2: W_x (rows 0..127 of W) -> transposed bf16 split [dir][n][k]
// =====================================================================
__global__ __launch_bounds__(128) void transpose_w(const float* __restrict__ Wfw,
                                                   const float* __restrict__ Wbw) {
    int blk = blockIdx.x;
    int dir = blk >> 9;
    int n   = blk & 511;
    int k   = threadIdx.x;
    const float* W = dir ? Wbw : Wfw;
    float f = W[(size_t)k * GG + n];
    __nv_bfloat16 hi = __float2bfloat16(f);
    size_t o = ((size_t)dir * 512 + n) * 128 + k;
    g_WtH[o] = hi;
    g_WtL[o] = __float2bfloat16(f - __bfloat162float(hi));
}

// =====================================================================
// Phase 1: persistent HMMA bf16-split GEMM (R12, kept unchanged).
// grid (18, 4, 2), block 256, smem 192 KB.
// =====================================================================
#define GMX 18
__global__ __launch_bounds__(256) void gemm_mma(const float* __restrict__ bfw,
                                                const float* __restrict__ bbw) {
    extern __shared__ unsigned char sm[];
    const int tid = threadIdx.x;
    const int n0 = blockIdx.y * 128;
    const int dir = blockIdx.z;
    const uint32_t sbase = smem_u32(sm);

    const __nv_bfloat16* BwH = g_WtH + ((size_t)dir * 512 + n0) * 128;
    const __nv_bfloat16* BwL = g_WtL + ((size_t)dir * 512 + n0) * 128;

    const int lr = tid >> 4, uq = tid & 15;

    // ---- B tiles (resident) ----
#pragma unroll
    for (int it = 0; it < 8; it++) {
        int r = lr + 16 * it;
        int u2 = (uq & 8) | ((uq ^ r) & 7);
        CPA16(sbase + r * 256 + u2 * 16, BwH + (size_t)r * 128 + uq * 8);
        CPA16(sbase + 32768 + r * 256 + u2 * 16, BwL + (size_t)r * 128 + uq * 8);
    }
    CPA_COMMIT();

    int job = blockIdx.x;
    {
        const size_t a0 = (size_t)job * 128 * 128;
#pragma unroll
        for (int it = 0; it < 8; it++) {
            int r = lr + 16 * it;
            int u2 = (uq & 8) | ((uq ^ r) & 7);
            CPA16(sbase + 65536 + r * 256 + u2 * 16, g_XH + a0 + (size_t)r * 128 + uq * 8);
            CPA16(sbase + 98304 + r * 256 + u2 * 16, g_XL + a0 + (size_t)r * 128 + uq * 8);
        }
        CPA_COMMIT();
    }
    CPA_WAIT(0);
    __syncthreads();

    const int w = tid >> 5, l = tid & 31;
    const int mb = (w & 3) * 32;
    const int nb = (w >> 2) * 64;

    const int rAl = mb + (l & 15);
    const int hA  = l >> 4;
    const int rBl = nb + (l & 7) + ((l >> 4) << 3);
    const int hB  = (l >> 3) & 1;

    const float* bias = dir ? bbw : bfw;
    const int gcol0 = n0 + nb + (l & 3) * 2;
    float2 bs[8];
#pragma unroll
    for (int ni = 0; ni < 8; ni++) bs[ni] = *(const float2*)(bias + gcol0 + ni * 8);
    float* Zb = g_Z + (size_t)dir * ((size_t)MM * GG);

    int cb = 0;
    while (job < 1024) {
        const int nxt = job + GMX;
        if (nxt < 1024) {
            const size_t a0 = (size_t)nxt * 128 * 128;
            const uint32_t ab = sbase + 65536u + (cb ^ 1) * 65536u;
#pragma unroll
            for (int it = 0; it < 8; it++) {
                int r = lr + 16 * it;
                int u2 = (uq & 8) | ((uq ^ r) & 7);
                CPA16(ab + r * 256 + u2 * 16, g_XH + a0 + (size_t)r * 128 + uq * 8);
                CPA16(ab + 32768 + r * 256 + u2 * 16, g_XL + a0 + (size_t)r * 128 + uq * 8);
            }
            CPA_COMMIT();
            CPA_WAIT(1);
        } else {
            CPA_WAIT(0);
        }
        __syncthreads();

        float c[2][8][4];
#pragma unroll
        for (int mi = 0; mi < 2; mi++)
#pragma unroll
            for (int ni = 0; ni < 8; ni++)
#pragma unroll
                for (int q = 0; q < 4; q++) c[mi][ni][q] = 0.0f;

        const uint32_t Abase = sbase + 65536u + cb * 65536u;
#pragma unroll
        for (int p = 0; p < 3; p++) {
            const uint32_t Ab = Abase + (p == 1 ? 32768u : 0u);
            const uint32_t Bb = sbase + (p == 2 ? 32768u : 0u);
#pragma unroll
            for (int kc = 0; kc < 8; kc++) {
                uint32_t a[2][4];
#pragma unroll
                for (int mi = 0; mi < 2; mi++) {
                    int row = rAl + mi * 16;
                    int u = kc * 2 + hA;
                    uint32_t addr = Ab + row * 256 + ((u & 8) | ((u ^ row) & 7)) * 16;
                    ldsm_x4(addr, a[mi]);
                }
                uint32_t b[4][4];
#pragma unroll
                for (int ni2 = 0; ni2 < 4; ni2++) {
                    int row = rBl + ni2 * 16;
                    int u = kc * 2 + hB;
                    uint32_t addr = Bb + row * 256 + ((u & 8) | ((u ^ row) & 7)) * 16;
                    ldsm_x4(addr, b[ni2]);
                }
#pragma unroll
                for (int mi = 0; mi < 2; mi++)
#pragma unroll
                    for (int ni = 0; ni < 8; ni++)
                        mma_bf16(c[mi][ni], a[mi], b[ni >> 1][(ni & 1) * 2],
                                 b[ni >> 1][(ni & 1) * 2 + 1]);
            }
        }

        const int grow0 = job * 128 + mb + (l >> 2);
#pragma unroll
        for (int mi = 0; mi < 2; mi++) {
            float* r0 = Zb + (size_t)(grow0 + mi * 16) * GG;
            float* r1 = r0 + (size_t)8 * GG;
#pragma unroll
            for (int ni = 0; ni < 8; ni++) {
                float2 v0 = make_float2(c[mi][ni][0] + bs[ni].x, c[mi][ni][1] + bs[ni].y);
                float2 v1 = make_float2(c[mi][ni][2] + bs[ni].x, c[mi][ni][3] + bs[ni].y);
                *(float2*)(r0 + gcol0 + ni * 8) = v0;
                *(float2*)(r1 + gcol0 + ni * 8) = v1;
            }
        }

        __syncthreads();
        cb ^= 1;
        job = nxt;
    }
}

// =====================================================================
// Phase 2: persistent recurrence, TWO sequences per CTA (same direction,
// batches b and b+32) sharing the weight registers/smem.
// grid 64, block 256. Thread t owns gate-cols t and t+256 (R2 layout).
//   rows 0..87   -> 44 f32x2 register pairs per column (176 regs)
//   rows 88..127 -> 10 ulonglong2 blocks per column in smem (81920 B)
// Interleaved dual-sequence FMA (weights read once, used for both h's).
// Same zs-exchange / replicated-epilogue dataflow as R2, doubled.
// =====================================================================
#define RECTHR 256
#define SMBLK  10
#define RPAIR  44

__global__ __launch_bounds__(RECTHR) void lstm_rec(
    const float* __restrict__ Wfw,
    const float* __restrict__ Wbw,
    float* __restrict__ out) {
    const int tid = threadIdx.x;
    const int j0  = tid;             // gate column A
    const int j1  = tid + 256;       // gate column B
    const int dir = blockIdx.x & 1;
    const int b   = blockIdx.x >> 1;         // 0..31 ; sequences b and b+32
    const float* W  = dir ? Wbw : Wfw;
    const float* Wh = W + FF * GG;   // rows 128..255 = W_h

    extern __shared__ unsigned char sraw[];
    ulonglong2* ws = (ulonglong2*)sraw;                          // 10*512*16 = 81920 B
    float* zs    = (float*)(sraw + SMBLK * 512 * 16);            // 1024 floats (2 seqs)
    float* hbuf1 = (float*)(sraw + SMBLK * 512 * 16 + 4096);     // 128 floats
    float* hbuf2 = (float*)(sraw + SMBLK * 512 * 16 + 4096 + 512);

    // ---- load weights: rows 0..87 in regs ----
    unsigned long long w0[RPAIR];   // col j0, pairs 0..43
    unsigned long long w1[RPAIR];   // col j1
#pragma unroll
    for (int p = 0; p < RPAIR; p++) {
        w0[p] = pk(Wh[(size_t)(2 * p) * GG + j0], Wh[(size_t)(2 * p + 1) * GG + j0]);
        w1[p] = pk(Wh[(size_t)(2 * p) * GG + j1], Wh[(size_t)(2 * p + 1) * GG + j1]);
    }
    // rows 88..127 in smem (10 blocks of 4 rows)
#pragma unroll
    for (int q = 0; q < SMBLK; q++) {
        int r = 88 + 4 * q;
        ulonglong2 vA, vB;
        vA.x = pk(Wh[(size_t)(r + 0) * GG + j0], Wh[(size_t)(r + 1) * GG + j0]);
        vA.y = pk(Wh[(size_t)(r + 2) * GG + j0], Wh[(size_t)(r + 3) * GG + j0]);
        vB.x = pk(Wh[(size_t)(r + 0) * GG + j1], Wh[(size_t)(r + 1) * GG + j1]);
        vB.y = pk(Wh[(size_t)(r + 2) * GG + j1], Wh[(size_t)(r + 3) * GG + j1]);
        ws[q * 512 + j0] = vA;
        ws[q * 512 + j1] = vB;
    }
    if (tid < UU) { hbuf1[tid] = 0.0f; hbuf2[tid] = 0.0f; }
    float c1 = 0.0f, c2 = 0.0f;
    __syncthreads();

    // ---- z streams for both sequences (prefetch one step ahead) ----
    const size_t zb1 = ((size_t)dir * MM + (size_t)b * TT) * GG;
    const size_t zb2 = ((size_t)dir * MM + (size_t)(b + 32) * TT) * GG;
    const float *zp1, *zp2;
    long long zstep;
    int tt0;
    if (dir == 0) { zp1 = g_Z + zb1; zp2 = g_Z + zb2;          zstep =  GG; tt0 = 0; }
    else { zp1 = g_Z + zb1 + (size_t)(TT - 1) * GG;
           zp2 = g_Z + zb2 + (size_t)(TT - 1) * GG;            zstep = -GG; tt0 = TT - 1; }
    float zn10 = zp1[j0], zn11 = zp1[j1];
    float zn20 = zp2[j0], zn21 = zp2[j1];

    float* outp1 = out + ((size_t)b * TT + tt0) * (2 * UU) + dir * UU + tid;        // tid<128
    float* outp2 = out + ((size_t)(b + 32) * TT + tt0) * (2 * UU) + dir * UU + tid;
    const long long ostep = (dir == 0) ? (2 * UU) : -(2 * UU);
    const int q4 = tid & 127;

    for (int t = 0; t < TT; t++) {
        float zc10 = zn10, zc11 = zn11, zc20 = zn20, zc21 = zn21;
        if (t + 1 < TT) {
            zp1 += zstep; zp2 += zstep;
            zn10 = zp1[j0]; zn11 = zp1[j1];
            zn20 = zp2[j0]; zn21 = zp2[j1];
        }

        const ulonglong2* hA = (const ulonglong2*)hbuf1;   // hA[p] = h1 rows 4p..4p+3
        const ulonglong2* hB = (const ulonglong2*)hbuf2;

        // 8 accumulators: a.. = seq1, b.. = seq2
        unsigned long long a00 = 0ull, a01 = 0ull, a10 = 0ull, a11 = 0ull;
        unsigned long long b00 = 0ull, b01 = 0ull, b10 = 0ull, b11 = 0ull;
#pragma unroll
        for (int p = 0; p < 22; p++) {                     // rows 0..87 (registers)
            ulonglong2 h1 = hA[p];
            ulonglong2 h2 = hB[p];
            unsigned long long wa = w0[2 * p], wb = w0[2 * p + 1];
            unsigned long long wc = w1[2 * p], wd = w1[2 * p + 1];
            a00 = fma2(wa, h1.x, a00);  b00 = fma2(wa, h2.x, b00);
            a01 = fma2(wb, h1.y, a01);  b01 = fma2(wb, h2.y, b01);
            a10 = fma2(wc, h1.x, a10);  b10 = fma2(wc, h2.x, b10);
            a11 = fma2(wd, h1.y, a11);  b11 = fma2(wd, h2.y, b11);
        }
#pragma unroll
        for (int q = 0; q < SMBLK; q++) {                  // rows 88..127 (smem, read ONCE)
            ulonglong2 h1 = hA[22 + q];
            ulonglong2 h2 = hB[22 + q];
            ulonglong2 wA = ws[q * 512 + j0];
            ulonglong2 wB = ws[q * 512 + j1];
            a00 = fma2(wA.x, h1.x, a00);  b00 = fma2(wA.x, h2.x, b00);
            a01 = fma2(wA.y, h1.y, a01);  b01 = fma2(wA.y, h2.y, b01);
            a10 = fma2(wB.x, h1.x, a10);  b10 = fma2(wB.x, h2.x, b10);
            a11 = fma2(wB.y, h1.y, a11);  b11 = fma2(wB.y, h2.y, b11);
        }

        float2 s0, s1;
        s0 = upk(a00); s1 = upk(a01);
        float z10 = (s0.x + s0.y) + (s1.x + s1.y) + zc10;
        s0 = upk(a10); s1 = upk(a11);
        float z11 = (s0.x + s0.y) + (s1.x + s1.y) + zc11;
        s0 = upk(b00); s1 = upk(b01);
        float z20 = (s0.x + s0.y) + (s1.x + s1.y) + zc20;
        s0 = upk(b10); s1 = upk(b11);
        float z21 = (s0.x + s0.y) + (s1.x + s1.y) + zc21;

        // activations (col j0: gate i or j ; col j1: gate f or o)
        float a1c0, a1c1, a2c0, a2c1;
        if (tid < 128) {
            a1c0 = sigmA(z10);  a1c1 = sigmA(z11 + 1.0f);
            a2c0 = sigmA(z20);  a2c1 = sigmA(z21 + 1.0f);
        } else {
            a1c0 = tanhA(z10);  a1c1 = sigmA(z11);
            a2c0 = tanhA(z20);  a2c1 = sigmA(z21);
        }
        zs[j0] = a1c0;  zs[j1] = a1c1;
        zs[512 + j0] = a2c0;  zs[512 + j1] = a2c1;
        __syncthreads();

        // replicated epilogue (threads q4 and q4+128 identical)
        float ai = zs[q4], aj = zs[q4 + 128], af = zs[q4 + 256], ao = zs[q4 + 384];
        c1 = fmaf(c1, af, ai * aj);
        float h1v = ao * tanhA(c1);
        ai = zs[512 + q4]; aj = zs[512 + q4 + 128];
        af = zs[512 + q4 + 256]; ao = zs[512 + q4 + 384];
        c2 = fmaf(c2, af, ai * aj);
        float h2v = ao * tanhA(c2);

        if (tid < UU) {
            hbuf1[tid] = h1v;
            hbuf2[tid] = h2v;
            *outp1 = h1v;
            *outp2 = h2v;
            outp1 += ostep;
            outp2 += ostep;
        }
        __syncthreads();
    }
}

extern "C" void kernel_launch(void* const* d_in, const int* in_sizes, int n_in,
                              void* d_out, int out_size) {
    const float* x   = (const float*)d_in[0];
    const float* Wfw = (const float*)d_in[1];
    const float* bfw = (const float*)d_in[2];
    const float* Wbw = (const float*)d_in[3];
    const float* bbw = (const float*)d_in[4];
    float* out = (float*)d_out;

    cudaFuncSetAttribute(gemm_mma, cudaFuncAttributeMaxDynamicSharedMemorySize, 196608);
    const int recSmem = SMBLK * 512 * 16 + 4096 + 1024 + 256;  // 87296
    cudaFuncSetAttribute(lstm_rec, cudaFuncAttributeMaxDynamicSharedMemorySize, recSmem);

    convert_x<<<8192, 256>>>(x);
    transpose_w<<<1024, 128>>>(Wfw, Wbw);
    dim3 gg(GMX, 4, 2);
    gemm_mma<<<gg, 256, 196608>>>(bfw, bbw);
    lstm_rec<<<64, RECTHR, recSmem>>>(Wfw, Wbw, out);
}

// round 15
// speedup vs baseline: 2.0492x; 2.0492x over previous
#include <cuda_runtime.h>
#include <cuda_bf16.h>
#include <cuda_fp16.h>
#include <cstdint>
#include <cstddef>

// Problem constants
#define BB 64
#define TT 2048
#define FF 128
#define UU 128
#define GG 512               // 4*U
#define MM (BB * TT)         // 131072 rows of x

// Scratch buffers (static __device__; allocation is forbidden)
__device__ float g_Z[2ull * 131072ull * 512ull];                 // z = x@Wx + b, both dirs
__device__ __align__(16) __nv_bfloat16 g_XH[131072ull * 128ull]; // x hi (bf16)
__device__ __align__(16) __nv_bfloat16 g_XL[131072ull * 128ull]; // x lo
__device__ __align__(16) __nv_bfloat16 g_WtH[2ull * 512ull * 128ull]; // W_x^T hi [dir][n][k]
__device__ __align__(16) __nv_bfloat16 g_WtL[2ull * 512ull * 128ull]; // W_x^T lo

// ---------------- f32x2 packed helpers ----------------
__device__ __forceinline__ unsigned long long fma2(unsigned long long a,
                                                   unsigned long long b,
                                                   unsigned long long c) {
    unsigned long long d;
    asm("fma.rn.f32x2 %0, %1, %2, %3;" : "=l"(d) : "l"(a), "l"(b), "l"(c));
    return d;
}
__device__ __forceinline__ unsigned long long pk(float x, float y) {
    unsigned long long d;
    asm("mov.b64 %0, {%1, %2};" : "=l"(d) : "f"(x), "f"(y));
    return d;
}
__device__ __forceinline__ float2 upk(unsigned long long a) {
    float2 r;
    asm("mov.b64 {%0, %1}, %2;" : "=f"(r.x), "=f"(r.y) : "l"(a));
    return r;
}

// ---------------- activations (HW tanh unit) ----------------
__device__ __forceinline__ float tanhA(float x) {
    float y;
    asm("tanh.approx.f32 %0, %1;" : "=f"(y) : "f"(x));
    return y;
}
__device__ __forceinline__ float sigmA(float x) {
    return fmaf(0.5f, tanhA(0.5f * x), 0.5f);
}

// ---------------- mma.sync / cp.async helpers ----------------
__device__ __forceinline__ uint32_t smem_u32(const void* p) {
    uint32_t a;
    asm("{ .reg .u64 t; cvta.to.shared.u64 t, %1; cvt.u32.u64 %0, t; }" : "=r"(a) : "l"(p));
    return a;
}
__device__ __forceinline__ void ldsm_x4(uint32_t addr, uint32_t* r) {
    asm volatile("ldmatrix.sync.aligned.m8n8.x4.shared.b16 {%0,%1,%2,%3}, [%4];"
                 : "=r"(r[0]), "=r"(r[1]), "=r"(r[2]), "=r"(r[3]) : "r"(addr));
}
__device__ __forceinline__ void mma_bf16(float* c, const uint32_t* a,
                                         uint32_t b0, uint32_t b1) {
    asm volatile("mma.sync.aligned.m16n8k16.row.col.f32.bf16.bf16.f32 "
                 "{%0,%1,%2,%3}, {%4,%5,%6,%7}, {%8,%9}, {%0,%1,%2,%3};"
                 : "+f"(c[0]), "+f"(c[1]), "+f"(c[2]), "+f"(c[3])
                 : "r"(a[0]), "r"(a[1]), "r"(a[2]), "r"(a[3]), "r"(b0), "r"(b1));
}
#define CPA16(dst, src) \
    asm volatile("cp.async.cg.shared.global [%0], [%1], 16;" \
                 :: "r"(dst), "l"((const void*)(src)) : "memory")
#define CPA_COMMIT() asm volatile("cp.async.commit_group;" ::: "memory")
#define CPA_WAIT(n)  asm volatile("cp.async.wait_group %0;" :: "n"(n) : "memory")

// =====================================================================
// Prep 1: x (fp32) -> XH, XL (bf16 split). 8 elems/thread.
// =====================================================================
__global__ __launch_bounds__(256) void convert_x(const float* __restrict__ x) {
    size_t i = ((size_t)blockIdx.x * 256 + threadIdx.x) * 8;
    float4 a = *(const float4*)(x + i);
    float4 b = *(const float4*)(x + i + 4);
    float f[8] = {a.x, a.y, a.z, a.w, b.x, b.y, b.z, b.w};
    union { __nv_bfloat16 h[8]; uint4 u; } H, L;
#pragma unroll
    for (int e = 0; e < 8; e++) {
        __nv_bfloat16 hi = __float2bfloat16(f[e]);
        H.h[e] = hi;
        L.h[e] = __float2bfloat16(f[e] - __bfloat162float(hi));
    }
    *(uint4*)(g_XH + i) = H.u;
    *(uint4*)(g_XL + i) = L.u;
}

// =====================================================================
// Prep 2: W_x (rows 0..127 of W) -> transposed bf16 split [dir][n][k]
// =====================================================================
__global__ __launch_bounds__(128) void transpose_w(const float* __restrict__ Wfw,
                                                   const float* __restrict__ Wbw) {
    int blk = blockIdx.x;
    int dir = blk >> 9;
    int n   = blk & 511;
    int k   = threadIdx.x;
    const float* W = dir ? Wbw : Wfw;
    float f = W[(size_t)k * GG + n];
    __nv_bfloat16 hi = __float2bfloat16(f);
    size_t o = ((size_t)dir * 512 + n) * 128 + k;
    g_WtH[o] = hi;
    g_WtL[o] = __float2bfloat16(f - __bfloat162float(hi));
}

// =====================================================================
// Phase 1: persistent HMMA bf16-split GEMM (R12, kept unchanged).
// grid (18, 4, 2), block 256, smem 192 KB.
// =====================================================================
#define GMX 18
__global__ __launch_bounds__(256) void gemm_mma(const float* __restrict__ bfw,
                                                const float* __restrict__ bbw) {
    extern __shared__ unsigned char sm[];
    const int tid = threadIdx.x;
    const int n0 = blockIdx.y * 128;
    const int dir = blockIdx.z;
    const uint32_t sbase = smem_u32(sm);

    const __nv_bfloat16* BwH = g_WtH + ((size_t)dir * 512 + n0) * 128;
    const __nv_bfloat16* BwL = g_WtL + ((size_t)dir * 512 + n0) * 128;

    const int lr = tid >> 4, uq = tid & 15;

    // ---- B tiles (resident) ----
#pragma unroll
    for (int it = 0; it < 8; it++) {
        int r = lr + 16 * it;
        int u2 = (uq & 8) | ((uq ^ r) & 7);
        CPA16(sbase + r * 256 + u2 * 16, BwH + (size_t)r * 128 + uq * 8);
        CPA16(sbase + 32768 + r * 256 + u2 * 16, BwL + (size_t)r * 128 + uq * 8);
    }
    CPA_COMMIT();

    int job = blockIdx.x;
    {
        const size_t a0 = (size_t)job * 128 * 128;
#pragma unroll
        for (int it = 0; it < 8; it++) {
            int r = lr + 16 * it;
            int u2 = (uq & 8) | ((uq ^ r) & 7);
            CPA16(sbase + 65536 + r * 256 + u2 * 16, g_XH + a0 + (size_t)r * 128 + uq * 8);
            CPA16(sbase + 98304 + r * 256 + u2 * 16, g_XL + a0 + (size_t)r * 128 + uq * 8);
        }
        CPA_COMMIT();
    }
    CPA_WAIT(0);
    __syncthreads();

    const int w = tid >> 5, l = tid & 31;
    const int mb = (w & 3) * 32;
    const int nb = (w >> 2) * 64;

    const int rAl = mb + (l & 15);
    const int hA  = l >> 4;
    const int rBl = nb + (l & 7) + ((l >> 4) << 3);
    const int hB  = (l >> 3) & 1;

    const float* bias = dir ? bbw : bfw;
    const int gcol0 = n0 + nb + (l & 3) * 2;
    float2 bs[8];
#pragma unroll
    for (int ni = 0; ni < 8; ni++) bs[ni] = *(const float2*)(bias + gcol0 + ni * 8);
    float* Zb = g_Z + (size_t)dir * ((size_t)MM * GG);

    int cb = 0;
    while (job < 1024) {
        const int nxt = job + GMX;
        if (nxt < 1024) {
            const size_t a0 = (size_t)nxt * 128 * 128;
            const uint32_t ab = sbase + 65536u + (cb ^ 1) * 65536u;
#pragma unroll
            for (int it = 0; it < 8; it++) {
                int r = lr + 16 * it;
                int u2 = (uq & 8) | ((uq ^ r) & 7);
                CPA16(ab + r * 256 + u2 * 16, g_XH + a0 + (size_t)r * 128 + uq * 8);
                CPA16(ab + 32768 + r * 256 + u2 * 16, g_XL + a0 + (size_t)r * 128 + uq * 8);
            }
            CPA_COMMIT();
            CPA_WAIT(1);
        } else {
            CPA_WAIT(0);
        }
        __syncthreads();

        float c[2][8][4];
#pragma unroll
        for (int mi = 0; mi < 2; mi++)
#pragma unroll
            for (int ni = 0; ni < 8; ni++)
#pragma unroll
                for (int q = 0; q < 4; q++) c[mi][ni][q] = 0.0f;

        const uint32_t Abase = sbase + 65536u + cb * 65536u;
#pragma unroll
        for (int p = 0; p < 3; p++) {
            const uint32_t Ab = Abase + (p == 1 ? 32768u : 0u);
            const uint32_t Bb = sbase + (p == 2 ? 32768u : 0u);
#pragma unroll
            for (int kc = 0; kc < 8; kc++) {
                uint32_t a[2][4];
#pragma unroll
                for (int mi = 0; mi < 2; mi++) {
                    int row = rAl + mi * 16;
                    int u = kc * 2 + hA;
                    uint32_t addr = Ab + row * 256 + ((u & 8) | ((u ^ row) & 7)) * 16;
                    ldsm_x4(addr, a[mi]);
                }
                uint32_t b[4][4];
#pragma unroll
                for (int ni2 = 0; ni2 < 4; ni2++) {
                    int row = rBl + ni2 * 16;
                    int u = kc * 2 + hB;
                    uint32_t addr = Bb + row * 256 + ((u & 8) | ((u ^ row) & 7)) * 16;
                    ldsm_x4(addr, b[ni2]);
                }
#pragma unroll
                for (int mi = 0; mi < 2; mi++)
#pragma unroll
                    for (int ni = 0; ni < 8; ni++)
                        mma_bf16(c[mi][ni], a[mi], b[ni >> 1][(ni & 1) * 2],
                                 b[ni >> 1][(ni & 1) * 2 + 1]);
            }
        }

        const int grow0 = job * 128 + mb + (l >> 2);
#pragma unroll
        for (int mi = 0; mi < 2; mi++) {
            float* r0 = Zb + (size_t)(grow0 + mi * 16) * GG;
            float* r1 = r0 + (size_t)8 * GG;
#pragma unroll
            for (int ni = 0; ni < 8; ni++) {
                float2 v0 = make_float2(c[mi][ni][0] + bs[ni].x, c[mi][ni][1] + bs[ni].y);
                float2 v1 = make_float2(c[mi][ni][2] + bs[ni].x, c[mi][ni][3] + bs[ni].y);
                *(float2*)(r0 + gcol0 + ni * 8) = v0;
                *(float2*)(r1 + gcol0 + ni * 8) = v1;
            }
        }

        __syncthreads();
        cb ^= 1;
        job = nxt;
    }
}

// =====================================================================
// Phase 2: persistent recurrence — R11 structure (best measured: 1452us),
// single change: smem-resident weight rows 100..127 stored as fp16
// (halves the spread smem crossbar traffic; converted with H2F in-loop).
// 256 threads, thread t owns gate-columns t and t+256:
//   rows 0..99   -> 50 packed f32x2 register pairs per column (200 regs, fp32)
//   rows 100..127-> 7 u64 blocks per column in smem, 4 fp16 weights each
// grid = 128, block = 256
// =====================================================================
#define RECTHR 256
#define SMBLK  7
#define RPAIR  50

__global__ __launch_bounds__(RECTHR) void lstm_rec(
    const float* __restrict__ Wfw,
    const float* __restrict__ Wbw,
    float* __restrict__ out) {
    const int tid = threadIdx.x;
    const int j0  = tid;             // gate column A
    const int j1  = tid + 256;       // gate column B
    const int dir = blockIdx.x & 1;
    const int b   = blockIdx.x >> 1;
    const float* W  = dir ? Wbw : Wfw;
    const float* Wh = W + FF * GG;   // rows 128..255 = W_h

    extern __shared__ unsigned char sraw[];
    // ws16[q*512 + col] : u64 = 4 fp16 weights for rows 100+4q .. 103+4q
    unsigned long long* ws16 = (unsigned long long*)sraw;       // 7*512*8 = 28672 B
    float* zs   = (float*)(sraw + SMBLK * 512 * 8);             // 512 floats
    float* hbuf = (float*)(sraw + SMBLK * 512 * 8 + 2048);      // 128 floats, 16B aligned

    // ---- load weights: fp32 register part (rows 0..99) ----
    unsigned long long w0[2 * RPAIR];   // column j0: pairs 0..49
    unsigned long long w1[2 * RPAIR];   // column j1
#pragma unroll
    for (int p = 0; p < RPAIR; p++) {
        w0[p] = pk(Wh[(size_t)(2 * p) * GG + j0], Wh[(size_t)(2 * p + 1) * GG + j0]);
        w1[p] = pk(Wh[(size_t)(2 * p) * GG + j1], Wh[(size_t)(2 * p + 1) * GG + j1]);
    }
    // ---- fp16 smem part (rows 100..127) ----
#pragma unroll
    for (int q = 0; q < SMBLK; q++) {
        int r = 100 + 4 * q;
#pragma unroll
        for (int cc = 0; cc < 2; cc++) {
            int col = cc ? j1 : j0;
            __half2 p01 = __floats2half2_rn(Wh[(size_t)(r + 0) * GG + col],
                                            Wh[(size_t)(r + 1) * GG + col]);
            __half2 p23 = __floats2half2_rn(Wh[(size_t)(r + 2) * GG + col],
                                            Wh[(size_t)(r + 3) * GG + col]);
            unsigned int u0 = *(unsigned int*)&p01;
            unsigned int u1 = *(unsigned int*)&p23;
            ws16[q * 512 + col] = (unsigned long long)u0 |
                                  ((unsigned long long)u1 << 32);
        }
    }
    if (tid < UU) hbuf[tid] = 0.0f;
    float c = 0.0f;
    __syncthreads();

    // ---- z stream (prefetch one step ahead) ----
    const size_t base = ((size_t)dir * MM + (size_t)b * TT) * GG;
    const float* zp;
    long long zstep;
    int tt0;
    if (dir == 0) { zp = g_Z + base;                          zstep =  GG; tt0 = 0; }
    else          { zp = g_Z + base + (size_t)(TT - 1) * GG;  zstep = -GG; tt0 = TT - 1; }
    float zn0 = zp[j0], zn1 = zp[j1];

    float* outp = out + ((size_t)b * TT + tt0) * (2 * UU) + dir * UU + tid; // valid iff tid<128
    const long long ostep = (dir == 0) ? (2 * UU) : -(2 * UU);
    const int q4 = tid & 127;

    for (int t = 0; t < TT; t++) {
        float zc0 = zn0, zc1 = zn1;
        if (t + 1 < TT) { zp += zstep; zn0 = zp[j0]; zn1 = zp[j1]; }

        const ulonglong2* hb = (const ulonglong2*)hbuf;  // hb[p] = h pairs (2p, 2p+1)
        unsigned long long a00 = 0ull, a01 = 0ull, a10 = 0ull, a11 = 0ull;
#pragma unroll
        for (int p = 0; p < 25; p++) {                   // rows 0..99 (registers)
            ulonglong2 h2 = hb[p];
            a00 = fma2(w0[2 * p], h2.x, a00);
            a01 = fma2(w0[2 * p + 1], h2.y, a01);
            a10 = fma2(w1[2 * p], h2.x, a10);
            a11 = fma2(w1[2 * p + 1], h2.y, a11);
        }
#pragma unroll
        for (int qq = 0; qq < SMBLK; qq++) {             // rows 100..127 (fp16 smem)
            ulonglong2 h2 = hb[25 + qq];
            unsigned long long vA = ws16[qq * 512 + j0];
            unsigned long long vB = ws16[qq * 512 + j1];
            unsigned int a0 = (unsigned int)vA, a1 = (unsigned int)(vA >> 32);
            unsigned int b0 = (unsigned int)vB, b1 = (unsigned int)(vB >> 32);
            float2 fA0 = __half22float2(*(__half2*)&a0);
            float2 fA1 = __half22float2(*(__half2*)&a1);
            float2 fB0 = __half22float2(*(__half2*)&b0);
            float2 fB1 = __half22float2(*(__half2*)&b1);
            a00 = fma2(pk(fA0.x, fA0.y), h2.x, a00);
            a01 = fma2(pk(fA1.x, fA1.y), h2.y, a01);
            a10 = fma2(pk(fB0.x, fB0.y), h2.x, a10);
            a11 = fma2(pk(fB1.x, fB1.y), h2.y, a11);
        }
        float2 s0 = upk(a00), s1 = upk(a01);
        float2 s2 = upk(a10), s3 = upk(a11);
        float z0 = (s0.x + s0.y) + (s1.x + s1.y) + zc0;
        float z1 = (s2.x + s2.y) + (s3.x + s3.y) + zc1;

        // col j0: gate 0 (i, sigm) or 1 (j, tanh); col j1: gate 2 (f, sigm+1) or 3 (o, sigm)
        float act0, act1;
        if (tid < 128) { act0 = sigmA(z0);  act1 = sigmA(z1 + 1.0f); }
        else           { act0 = tanhA(z0);  act1 = sigmA(z1); }
        zs[j0] = act0;
        zs[j1] = act1;
        __syncthreads();

        // c/h update replicated in threads q4 and q4+128 (identical arithmetic)
        float ai = zs[q4], aj = zs[q4 + 128], af = zs[q4 + 256], ao = zs[q4 + 384];
        c = fmaf(c, af, ai * aj);
        float h = ao * tanhA(c);
        if (tid < UU) {
            hbuf[tid] = h;
            *outp = h;
            outp += ostep;
        }
        __syncthreads();
    }
}

extern "C" void kernel_launch(void* const* d_in, const int* in_sizes, int n_in,
                              void* d_out, int out_size) {
    const float* x   = (const float*)d_in[0];
    const float* Wfw = (const float*)d_in[1];
    const float* bfw = (const float*)d_in[2];
    const float* Wbw = (const float*)d_in[3];
    const float* bbw = (const float*)d_in[4];
    float* out = (float*)d_out;

    cudaFuncSetAttribute(gemm_mma, cudaFuncAttributeMaxDynamicSharedMemorySize, 196608);
    const int recSmem = SMBLK * 512 * 8 + 2048 + 512 + 256;  // 31488
    cudaFuncSetAttribute(lstm_rec, cudaFuncAttributeMaxDynamicSharedMemorySize, recSmem);

    convert_x<<<8192, 256>>>(x);
    transpose_w<<<1024, 128>>>(Wfw, Wbw);
    dim3 gg(GMX, 4, 2);
    gemm_mma<<<gg, 256, 196608>>>(bfw, bbw);
    lstm_rec<<<128, RECTHR, recSmem>>>(Wfw, Wbw, out);
}